// round 9
// baseline (speedup 1.0000x reference)
#include <cuda_runtime.h>
#include <cuda_bf16.h>

#define BB 4
#define MM 2048
#define HH 16
#define NJ 12
#define SCALE 0.3535533905932738f   // (128//16)^-0.5

__constant__ float c_F[NJ] = {
    1.0f, 1.0f, 5.0e-1f, 1.6666666666666666e-1f,
    4.1666666666666664e-2f, 8.3333333333333332e-3f,
    1.3888888888888889e-3f, 1.9841269841269841e-4f,
    2.4801587301587302e-5f, 2.7557319223985893e-6f,
    2.7557319223985894e-7f, 2.5052108385441720e-8f
};

__device__ float g_y[BB * MM];   // residual + attention output (pre-LN)
__device__ int   g_cnt[BB];      // zero-init; self-resetting every run

// Overlay layout (floats), region size 8448:
//   phase S (staging):  qf [0,4096) = (wq,wf) interleaved [s*256+2d+{0,1}]
//                       kvw[4096,8448) = (wk,wv) interleaved [d2*68+4t+{0..3}]
//   phase P (post-dot): Kpow [0,1536)      = [j*128+p]
//                       Qpow [1536,3120)   = [j*132+p]
//                       Apow [3120,6192)   = [j*256+s*16+t]
//                       iv   [3120,5232)   = [t*132+p]  (overwrites Apow later)

__global__ void __launch_bounds__(512, 1)
k_fused(const float* __restrict__ query, const float* __restrict__ key_,
        const float* __restrict__ value, const float* __restrict__ wq,
        const float* __restrict__ wk,    const float* __restrict__ wv,
        const float* __restrict__ wf,    const float* __restrict__ lnw,
        const float* __restrict__ lnb,   float* __restrict__ out) {
    const int b    = blockIdx.x >> 4;
    const int h    = blockIdx.x & 15;
    const int tid  = threadIdx.x;
    const int lane = tid & 31;
    const int warp = tid >> 5;

    __shared__ float ovl[8448];
    __shared__ float Ash[256];      // A(s,t) at [s*16+t]
    __shared__ float Gts[256];      // G(t,s) at [s*16+t]  (s-major!)
    __shared__ float Qs[128], Ks[128], Vs[128];
    __shared__ float SA[NJ * 16];   // [j*16+t]
    __shared__ float AG[NJ * 16];   // [j*16+t]
    __shared__ float cz[256];       // [t*16+j], j<12 used
    __shared__ float QMs[16];
    __shared__ float U[NJ * 16];    // [j*16+t]
    __shared__ float Wf[NJ];
    __shared__ float redS[16], redS2[16];
    __shared__ float mu_s, rs_s;
    __shared__ int   isLast;

    float* Kpow = ovl;
    float* Qpow = ovl + 1536;
    float* Apow = ovl + 3120;
    float* iv   = ovl + 3120;

    // ---- register prefetch: per-head q/k/v + LN params (for possible tail) ----
    float qv = 0.f, kval = 0.f, vval = 0.f;
    if (tid < 128) {
        int gi = b * MM + h * 128 + tid;
        qv = query[gi]; kval = key_[gi]; vval = value[gi];
    }
    const float4 lw4 = ((const float4*)lnw)[tid];
    const float4 lb4 = ((const float4*)lnb)[tid];

    // ---- stage weights: 4 f4 LDG + 4 f4 STS per thread ----
    {
        float4 a  = ((const float4*)wq)[tid];
        float4 f  = ((const float4*)wf)[tid];
        float4 kk = ((const float4*)wk)[tid];
        float4 vw = ((const float4*)wv)[tid];
        int st = tid >> 5, off = tid & 31;
        float* q0 = ovl + st * 256 + 8 * off;
        ((float4*)q0)[0] = make_float4(a.x, f.x, a.y, f.y);
        ((float4*)q0)[1] = make_float4(a.z, f.z, a.w, f.w);
        float* kb = ovl + 4096;
        *(float4*)(kb + (off * 2) * 68 + 4 * st)     = make_float4(kk.x, vw.x, kk.y, vw.y);
        *(float4*)(kb + (off * 2 + 1) * 68 + 4 * st) = make_float4(kk.z, vw.z, kk.w, vw.w);
    }
    if (tid < 128) { Qs[tid] = qv; Ks[tid] = kval; Vs[tid] = vval; }
    __syncthreads();

    // ---- A(s,t), G(t,s): 256 dual dots, 2 threads per pair ----
    {
        int pair = tid >> 1, c = tid & 1;
        int s = pair >> 4, t = pair & 15;
        const float4* qp = (const float4*)(ovl + s * 256);
        const float4* kp = (const float4*)(ovl + 4096 + 4 * t);
        float a = 0.f, g = 0.f;
#pragma unroll
        for (int i = 0; i < 32; i++) {
            int d2 = c + 2 * i;
            float4 q = qp[d2];
            float4 x = kp[d2 * 17];
            a = fmaf(q.x, x.x, a);  g = fmaf(q.y, x.y, g);
            a = fmaf(q.z, x.z, a);  g = fmaf(q.w, x.w, g);
        }
        a += __shfl_xor_sync(0xffffffffu, a, 1);
        g += __shfl_xor_sync(0xffffffffu, g, 1);
        if (c == 0) { Ash[s * 16 + t] = SCALE * a; Gts[s * 16 + t] = g; }
    }
    __syncthreads();   // staging dead -> overlay

    // ---- P1: K/Q powers (tid<128) || Apow table (tid 128..383) ----
    if (tid < 128) {
        float kp = 1.f, qp = 1.f;
#pragma unroll
        for (int j = 0; j < NJ; j++) {
            Kpow[j * 128 + tid] = kp;
            Qpow[j * 132 + tid] = qp;
            kp *= kval; qp *= qv;
        }
    } else if (tid < 384) {
        int idx = tid - 128;                 // idx = s*16 + t
        float a = Ash[idx];
        float pw = 1.f;
#pragma unroll
        for (int j = 0; j < NJ; j++) {
            Apow[j * 256 + idx] = pw;
            pw *= a;
        }
    }
    __syncthreads();

    // ---- P2: SA/AG reductions (tid<192) || QM_j (tid 192..287) ----
    if (tid < 192) {
        int j = tid >> 4, t = tid & 15;
        float sa = 0.f, ag = 0.f;
        const float* ap = Apow + j * 256 + t;
        const float* gp = Gts + t;
#pragma unroll
        for (int s = 0; s < 16; s++) {
            float pw = ap[s * 16];
            sa += pw;
            ag = fmaf(pw, gp[s * 16], ag);
        }
        SA[j * 16 + t] = sa;
        AG[j * 16 + t] = ag;
    } else if (tid < 288) {
        int idx = tid - 192;
        int j = idx >> 3, oct = idx & 7;     // 8 threads per j
        const float4* qp4 = (const float4*)(Qpow + j * 132) + oct * 4;
        float4 x0 = qp4[0], x1 = qp4[1], x2 = qp4[2], x3 = qp4[3];
        float s = ((x0.x + x0.y) + (x0.z + x0.w)) + ((x1.x + x1.y) + (x1.z + x1.w))
                + ((x2.x + x2.y) + (x2.z + x2.w)) + ((x3.x + x3.y) + (x3.z + x3.w));
        s += __shfl_xor_sync(0xffffffffu, s, 1);
        s += __shfl_xor_sync(0xffffffffu, s, 2);
        s += __shfl_xor_sync(0xffffffffu, s, 4);
        if (oct == 0) QMs[j] = s;
    }
    __syncthreads();

    // ---- P3: cz[t][j] = F_j * QM_j * SA_j(t) ----
    if (tid < 192) {
        int j = tid >> 4, t = tid & 15;
        cz[t * 16 + j] = c_F[j] * QMs[j] * SA[j * 16 + t];
    }
    __syncthreads();

    // ---- P4: Z(p,t) Horner; iv[t][p] = V_p / Z   (512 threads, 4 t's each) ----
    {
        int p = tid & 127, tq = tid >> 7;
        float k = Ks[p], v = Vs[p];
        const float4* c4 = (const float4*)cz;
#pragma unroll
        for (int tt = 0; tt < 4; tt++) {
            int t = tq * 4 + tt;
            float4 c0 = c4[t * 4 + 0];
            float4 c1 = c4[t * 4 + 1];
            float4 c2 = c4[t * 4 + 2];
            float z = c2.w;
            z = fmaf(z, k, c2.z); z = fmaf(z, k, c2.y); z = fmaf(z, k, c2.x);
            z = fmaf(z, k, c1.w); z = fmaf(z, k, c1.z); z = fmaf(z, k, c1.y);
            z = fmaf(z, k, c1.x);
            z = fmaf(z, k, c0.w); z = fmaf(z, k, c0.z); z = fmaf(z, k, c0.y);
            z = fmaf(z, k, c0.x);
            iv[t * 132 + p] = __fdividef(v, z);
        }
    }
    __syncthreads();

    // ---- P5: U[j][t] = sum_p Kpow[j][p]*iv[t][p]  (2 threads per element) ----
    if (tid < 384) {
        int jt = tid >> 1, c = tid & 1;
        int j = jt >> 4, t = jt & 15;
        const float4* kp4 = (const float4*)(Kpow + j * 128) + c * 16;
        const float4* iv4 = (const float4*)(iv + t * 132) + c * 16;
        float u = 0.f;
#pragma unroll
        for (int q = 0; q < 16; q++) {
            float4 a = kp4[q], x = iv4[q];
            u = fmaf(a.x, x.x, u); u = fmaf(a.y, x.y, u);
            u = fmaf(a.z, x.z, u); u = fmaf(a.w, x.w, u);
        }
        u += __shfl_xor_sync(0xffffffffu, u, 1);
        if (c == 0) U[j * 16 + t] = u;
    }
    __syncthreads();

    // ---- P6: Wf[j] = F_j * sum_t AG[j][t]*U[j][t] ----
    if (tid < NJ) {
        const float4* u4 = (const float4*)(U  + tid * 16);
        const float4* a4 = (const float4*)(AG + tid * 16);
        float s = 0.f;
#pragma unroll
        for (int q = 0; q < 4; q++) {
            float4 u = u4[q], a = a4[q];
            s = fmaf(u.x, a.x, s); s = fmaf(u.y, a.y, s);
            s = fmaf(u.z, a.z, s); s = fmaf(u.w, a.w, s);
        }
        Wf[tid] = c_F[tid] * s;
    }
    __syncthreads();

    // ---- P7: y = q + sum_j Wf[j] q^j -> g_y ----
    if (tid < 128) {
        float val = Wf[NJ - 1];
#pragma unroll
        for (int j = NJ - 2; j >= 0; j--) val = fmaf(val, qv, Wf[j]);
        g_y[b * MM + h * 128 + tid] = qv + val;
    }
    __syncthreads();

    // ---- arrival counter; only the last block of each batch does LN ----
    if (tid == 0) {
        __threadfence();
        int old = atomicAdd(&g_cnt[b], 1);
        isLast = (old == HH - 1);
    }
    __syncthreads();
    if (!isLast) return;
    __threadfence();   // acquire

    // ---- LN tail: 512 threads, 4 y's each (L1-bypass loads) ----
    float4 y4 = __ldcg(((const float4*)(g_y + b * MM)) + tid);
    float s1 = (y4.x + y4.y) + (y4.z + y4.w);
    float s2 = fmaf(y4.x, y4.x, fmaf(y4.y, y4.y, fmaf(y4.z, y4.z, y4.w * y4.w)));
#pragma unroll
    for (int o = 16; o; o >>= 1) {
        s1 += __shfl_down_sync(0xffffffffu, s1, o);
        s2 += __shfl_down_sync(0xffffffffu, s2, o);
    }
    if (lane == 0) { redS[warp] = s1; redS2[warp] = s2; }
    __syncthreads();
    if (warp == 0) {
        float a = (lane < 16) ? redS[lane]  : 0.f;
        float c = (lane < 16) ? redS2[lane] : 0.f;
#pragma unroll
        for (int o = 8; o; o >>= 1) {
            a += __shfl_xor_sync(0xffffffffu, a, o);
            c += __shfl_xor_sync(0xffffffffu, c, o);
        }
        if (lane == 0) {
            float mu  = a * (1.0f / MM);
            float var = c * (1.0f / MM) - mu * mu;
            mu_s = mu;
            rs_s = rsqrtf(var + 1e-5f);
        }
    }
    __syncthreads();
    const float mu = mu_s, rs = rs_s;
    float4 o4;
    o4.x = (y4.x - mu) * rs * lw4.x + lb4.x;
    o4.y = (y4.y - mu) * rs * lw4.y + lb4.y;
    o4.z = (y4.z - mu) * rs * lw4.z + lb4.z;
    o4.w = (y4.w - mu) * rs * lw4.w + lb4.w;
    ((float4*)(out + b * MM))[tid] = o4;
    if (tid == 0) g_cnt[b] = 0;   // reset for next graph replay
}

extern "C" void kernel_launch(void* const* d_in, const int* in_sizes, int n_in,
                              void* d_out, int out_size) {
    const float* query = (const float*)d_in[0];
    const float* key_  = (const float*)d_in[1];
    const float* value = (const float*)d_in[2];
    const float* wq    = (const float*)d_in[3];
    const float* wk    = (const float*)d_in[4];
    const float* wv    = (const float*)d_in[5];
    const float* wf    = (const float*)d_in[6];
    const float* lw    = (const float*)d_in[7];
    const float* lb    = (const float*)d_in[8];
    float* out = (float*)d_out;

    k_fused<<<BB * HH, 512>>>(query, key_, value, wq, wk, wv, wf, lw, lb, out);
}

// round 10
// speedup vs baseline: 1.0356x; 1.0356x over previous
#include <cuda_runtime.h>
#include <cuda_bf16.h>

#define BB 4
#define MM 2048
#define HH 16
#define NJ 10
#define SCALE   0.3535533905932738f    // (128//16)^-0.5
#define INV2048 4.8828125e-4f          // 1/2048 (exact)

__constant__ float c_F[NJ] = {
    1.0f, 1.0f, 0.5f, 0.16666666666666666f,
    0.041666666666666664f, 0.008333333333333333f,
    0.001388888888888889f, 1.984126984126984e-4f,
    2.48015873015873e-5f,  2.7557319223985893e-6f
};

// cross-block LN state (zero-init; self-resetting every run)
__device__ float2 g_part[BB * HH];
__device__ int    g_cnt[BB];
__device__ int    g_done[BB];

__global__ void __launch_bounds__(512, 1)
k_fused(const float* __restrict__ query, const float* __restrict__ key_,
        const float* __restrict__ value, const float* __restrict__ wq,
        const float* __restrict__ wk,    const float* __restrict__ wv,
        const float* __restrict__ wf,    const float* __restrict__ lnw,
        const float* __restrict__ lnb,   float* __restrict__ out) {
    const int b    = blockIdx.x >> 4;
    const int h    = blockIdx.x & 15;
    const int tid  = threadIdx.x;
    const int lane = tid & 31;
    const int warp = tid >> 5;

    // ovl: phase1 = staged weights Sq/Sf/Sk/Sv (4 x 2112, pad-132 rows);
    //      phase2 = iv[t*132+p] (2112) reuses the front.
    __shared__ float ovl[8448];
    __shared__ float AshT[256];     // SCALE*A(s,t) at [t*16+s]
    __shared__ float GtsT[256];     // G(t,s)      at [t*16+s]
    __shared__ float Qs[128], Ks[128], Vs[128];
    __shared__ float SAt[256];      // [t*16+j], j>=NJ zeroed
    __shared__ float AGj[256];      // [j*16+t], j<NJ used
    __shared__ float FQ[16];        // F_j*QM_j, j>=NJ zeroed
    __shared__ float Psh[256];      // [j*16+t] : U[j][t]*AG[j][t]
    __shared__ float Wfs[16];
    __shared__ float redS[4], redS2[4];
    __shared__ float mu_s, rs_s;

    float* Sq = ovl;
    float* Sf = ovl + 2112;
    float* Sk = ovl + 4224;
    float* Sv = ovl + 6336;
    float* iv = ovl;                // overlay after dots

    // ---- per-thread global inputs (issue LDGs early) ----
    float qv = 0.f, kval = 0.f, vval = 0.f, lwv = 0.f, lbv = 0.f;
    if (tid < 128) {
        int gi = b * MM + h * 128 + tid;
        qv = query[gi]; kval = key_[gi]; vval = value[gi];
        lwv = lnw[h * 128 + tid]; lbv = lnb[h * 128 + tid];
    }

    // ---- stage weights: plain padded rows [st*132 + d], 1 f4 each ----
    {
        int st = tid >> 5, off = tid & 31;
        int fi = st * 33 + off;     // f4 index into padded row
        ((float4*)Sq)[fi] = ((const float4*)wq)[tid];
        ((float4*)Sf)[fi] = ((const float4*)wf)[tid];
        ((float4*)Sk)[fi] = ((const float4*)wk)[tid];
        ((float4*)Sv)[fi] = ((const float4*)wv)[tid];
    }
    if (tid < 256) SAt[tid] = 0.f;
    if (tid < 16)  FQ[tid] = 0.f;
    if (tid < 128) { Qs[tid] = qv; Ks[tid] = kval; Vs[tid] = vval; }
    __syncthreads();

    // ---- dual GEMM 16x16x128: warps 0-7 -> A, warps 8-15 -> G ----
    {
        int isG  = warp >> 3;
        int sblk = (warp >> 2) & 1, tblk = warp & 3;
        int s = sblk * 8 + (lane >> 2);
        int t = tblk * 4 + (lane & 3);
        const float4* X = (const float4*)((isG ? Sf : Sq) + s * 132);
        const float4* Y = (const float4*)((isG ? Sv : Sk) + t * 132);
        float ax = 0.f, ay = 0.f, az = 0.f, aw = 0.f;
#pragma unroll
        for (int i = 0; i < 32; i++) {
            float4 x = X[i], y = Y[i];
            ax = fmaf(x.x, y.x, ax);
            ay = fmaf(x.y, y.y, ay);
            az = fmaf(x.z, y.z, az);
            aw = fmaf(x.w, y.w, aw);
        }
        float a = (ax + ay) + (az + aw);
        if (isG) GtsT[t * 16 + s] = a;
        else     AshT[t * 16 + s] = SCALE * a;
    }
    __syncthreads();

    // ---- warps 0-7: SA[t][j], AG[j][t] via register power recurrence ----
    if (warp < 8) {
        int t = warp * 2 + (lane >> 4);
        int s = lane & 15;
        float a = AshT[t * 16 + s];
        float g = GtsT[t * 16 + s];
        float pw = 1.f;
#pragma unroll
        for (int j = 0; j < NJ; j++) {
            float sa = pw, ag = pw * g;
            sa += __shfl_xor_sync(0xffffffffu, sa, 1);
            sa += __shfl_xor_sync(0xffffffffu, sa, 2);
            sa += __shfl_xor_sync(0xffffffffu, sa, 4);
            sa += __shfl_xor_sync(0xffffffffu, sa, 8);
            ag += __shfl_xor_sync(0xffffffffu, ag, 1);
            ag += __shfl_xor_sync(0xffffffffu, ag, 2);
            ag += __shfl_xor_sync(0xffffffffu, ag, 4);
            ag += __shfl_xor_sync(0xffffffffu, ag, 8);
            if ((lane & 15) == j) { SAt[t * 16 + j] = sa; AGj[j * 16 + t] = ag; }
            pw *= a;
        }
    } else if (warp == 8) {
        // ---- FQ[j] = F_j * QM_j,  QM_j = sum_p Q_p^j ----
        float4 q4 = ((const float4*)Qs)[lane];
        float px = 1.f, py = 1.f, pz = 1.f, pw4 = 1.f;
#pragma unroll
        for (int j = 0; j < NJ; j++) {
            float qm = (px + py) + (pz + pw4);
            qm += __shfl_xor_sync(0xffffffffu, qm, 1);
            qm += __shfl_xor_sync(0xffffffffu, qm, 2);
            qm += __shfl_xor_sync(0xffffffffu, qm, 4);
            qm += __shfl_xor_sync(0xffffffffu, qm, 8);
            qm += __shfl_xor_sync(0xffffffffu, qm, 16);
            if (lane == j) FQ[j] = c_F[j] * qm;
            px *= q4.x; py *= q4.y; pz *= q4.z; pw4 *= q4.w;
        }
    }
    __syncthreads();

    // ---- Z Horner + series reciprocal -> iv[t][p] = V_p * 2048/Z(p,t) ----
    {
        int p = tid & 127, tq = tid >> 7;
        float k = Ks[p], v = Vs[p];
        float4 f0 = ((const float4*)FQ)[0];
        float4 f1 = ((const float4*)FQ)[1];
        float4 f2 = ((const float4*)FQ)[2];
#pragma unroll
        for (int tt = 0; tt < 4; tt++) {
            int t = tq * 4 + tt;
            const float4* s4 = (const float4*)(SAt + t * 16);
            float4 s0 = s4[0], s1 = s4[1], s2 = s4[2];
            float z = f2.w * s2.w;                 // zero (padded)
            z = fmaf(z, k, f2.z * s2.z);
            z = fmaf(z, k, f2.y * s2.y);
            z = fmaf(z, k, f2.x * s2.x);
            z = fmaf(z, k, f1.w * s1.w);
            z = fmaf(z, k, f1.z * s1.z);
            z = fmaf(z, k, f1.y * s1.y);
            z = fmaf(z, k, f1.x * s1.x);
            z = fmaf(z, k, f0.w * s0.w);
            z = fmaf(z, k, f0.z * s0.z);
            z = fmaf(z, k, f0.y * s0.y);
            z = fmaf(z, k, f0.x * s0.x);           // includes c0 = 2048 exactly
            float e = fmaf(z, INV2048, -1.0f);     // eps, |eps| << 1
            float r = fmaf(-e, 1.0f, 1.0f);        // 1/(1+eps) series, err eps^7
            r = fmaf(-e, r, 1.0f);
            r = fmaf(-e, r, 1.0f);
            r = fmaf(-e, r, 1.0f);
            r = fmaf(-e, r, 1.0f);
            r = fmaf(-e, r, 1.0f);
            iv[t * 132 + p] = v * r;               // 1/2048 folded into Wf
        }
    }
    __syncthreads();

    // ---- U[j][t]*AG -> Psh : warp = t, K powers regenerated in registers ----
    {
        int t = warp;
        float4 iv4 = ((const float4*)(iv + t * 132))[lane];
        float4 k4  = ((const float4*)Ks)[lane];
        float kx = 1.f, ky = 1.f, kz = 1.f, kw = 1.f;
#pragma unroll
        for (int j = 0; j < NJ; j++) {
            float u = fmaf(kx, iv4.x, fmaf(ky, iv4.y, fmaf(kz, iv4.z, kw * iv4.w)));
            u += __shfl_xor_sync(0xffffffffu, u, 1);
            u += __shfl_xor_sync(0xffffffffu, u, 2);
            u += __shfl_xor_sync(0xffffffffu, u, 4);
            u += __shfl_xor_sync(0xffffffffu, u, 8);
            u += __shfl_xor_sync(0xffffffffu, u, 16);
            if (lane == j) Psh[j * 16 + t] = u * AGj[j * 16 + t];
            kx *= k4.x; ky *= k4.y; kz *= k4.z; kw *= k4.w;
        }
    }
    __syncthreads();

    // ---- Wf[j] = F_j/2048 * sum_t Psh[j][t] ----
    if (tid < NJ) {
        const float4* p4 = (const float4*)(Psh + tid * 16);
        float4 a = p4[0], c = p4[1], d = p4[2], e = p4[3];
        float s = ((a.x + a.y) + (a.z + a.w)) + ((c.x + c.y) + (c.z + c.w))
                + ((d.x + d.y) + (d.z + d.w)) + ((e.x + e.y) + (e.z + e.w));
        Wfs[tid] = c_F[tid] * INV2048 * s;
    }
    __syncthreads();

    // ---- y = q + sum_j Wf[j] q^j ; per-block LN partials ----
    float yv = 0.f;
    if (tid < 128) {
        float val = Wfs[NJ - 1];
#pragma unroll
        for (int j = NJ - 2; j >= 0; j--) val = fmaf(val, qv, Wfs[j]);
        yv = qv + val;
    }
    if (tid < 128) {
        float s1 = yv, s2 = yv * yv;
#pragma unroll
        for (int o = 16; o; o >>= 1) {
            s1 += __shfl_down_sync(0xffffffffu, s1, o);
            s2 += __shfl_down_sync(0xffffffffu, s2, o);
        }
        if (lane == 0) { redS[warp] = s1; redS2[warp] = s2; }
    }
    __syncthreads();

    // ---- publish partials, spin until all 16 heads arrived ----
    if (tid == 0) {
        float ps  = (redS[0]  + redS[1])  + (redS[2]  + redS[3]);
        float ps2 = (redS2[0] + redS2[1]) + (redS2[2] + redS2[3]);
        g_part[b * HH + h] = make_float2(ps, ps2);
        __threadfence();
        atomicAdd(&g_cnt[b], 1);
        while (((volatile int*)g_cnt)[b] < HH) { }
        __threadfence();
    }
    __syncthreads();

    // ---- every block computes mu/rs from the 16 partials (parallel reads) ----
    if (warp == 0) {
        float a = 0.f, c = 0.f;
        if (lane < HH) {
            float2 pp = __ldcg(&g_part[b * HH + lane]);
            a = pp.x; c = pp.y;
        }
#pragma unroll
        for (int o = 8; o; o >>= 1) {
            a += __shfl_xor_sync(0xffffffffu, a, o);
            c += __shfl_xor_sync(0xffffffffu, c, o);
        }
        if (lane == 0) {
            float mu  = a * (1.0f / MM);
            float var = c * (1.0f / MM) - mu * mu;
            mu_s = mu;
            rs_s = rsqrtf(var + 1e-5f);
        }
    }
    __syncthreads();
    if (tid < 128)
        out[b * MM + h * 128 + tid] = (yv - mu_s) * rs_s * lwv + lbv;

    // ---- reset counters for next graph replay ----
    if (tid == 0) {
        int old = atomicAdd(&g_done[b], 1);
        if (old == HH - 1) { g_cnt[b] = 0; g_done[b] = 0; }
    }
}

extern "C" void kernel_launch(void* const* d_in, const int* in_sizes, int n_in,
                              void* d_out, int out_size) {
    const float* query = (const float*)d_in[0];
    const float* key_  = (const float*)d_in[1];
    const float* value = (const float*)d_in[2];
    const float* wq    = (const float*)d_in[3];
    const float* wk    = (const float*)d_in[4];
    const float* wv    = (const float*)d_in[5];
    const float* wf    = (const float*)d_in[6];
    const float* lw    = (const float*)d_in[7];
    const float* lb    = (const float*)d_in[8];
    float* out = (float*)d_out;

    k_fused<<<BB * HH, 512>>>(query, key_, value, wq, wk, wv, wf, lw, lb, out);
}